// round 5
// baseline (speedup 1.0000x reference)
#include <cuda_runtime.h>
#include <cstdint>

// ============================================================================
// SIREN fused inference via int8 mma.sync m16n8k32 (sm_103-safe PTX).
// Fixed-point split: a*16256 = a1*128 + a2 ; w*65536 = w1*128 + w2 (int8).
// z = (acc_hh*2^14 + acc_cross*2^7) / (16256*65536)   [a2*w2 dropped, ~2e-5]
// 3 int8 MMAs per k32 = half the tensor instructions of the bf16 3-MMA split.
// Bulk-synchronous layers; weights int8-packed, streamed L2->SMEM (cp.async,
// k128 double-buffered chunks); ldmatrix B broadcast from SMEM.
// ============================================================================

#define THREADS    256
#define M_TILE     64
#define N_POINTS   1048576
#define GRID_CTAS  (N_POINTS / M_TILE)      // 16384

// --- SMEM layout (bytes) ---
#define A_LDB      272                       // 256 k bytes + 16 pad
#define A_PLANE    (64 * A_LDB)              // 17408 (planes: a1, a2)
#define AB_OFF     0
#define WBUF_OFF   (2 * A_PLANE)             // 34816
#define W_LDB      144                       // 128 k bytes + 16 pad
#define W_PLANE    (256 * W_LDB)             // 36864 (planes: w1, w2)
#define W_CHUNK    (2 * W_PLANE)             // 73728 (k128 chunk)
#define W0S_OFF    (WBUF_OFF + 2 * W_CHUNK)  // 182272
#define B0S_OFF    (W0S_OFF + 3072)
#define BIAS_OFF   (B0S_OFF + 1024)
#define WFS_OFF    (BIAS_OFF + 4096)
#define RED_OFF    (WFS_OFF + 1024)
#define SMEM_TOTAL (RED_OFF + 1024)          // 192512

// int8-packed weights: [layer(4)][chunk(2)] x {w1 plane, w2 plane}
__device__ __align__(128) unsigned char g_wpacked[4 * 2 * W_CHUNK];

// ---------------------------------------------------------------------------
// helpers
// ---------------------------------------------------------------------------
__device__ __forceinline__ uint32_t smem_u32(const void* p) {
    uint32_t a;
    asm("{ .reg .u64 t; cvta.to.shared.u64 t, %1; cvt.u32.u64 %0, t; }"
        : "=r"(a) : "l"(p));
    return a;
}

#define CP_ASYNC16(dst, src) \
    asm volatile("cp.async.cg.shared.global [%0], [%1], 16;" :: "r"(dst), "l"(src) : "memory")
#define CP_COMMIT() asm volatile("cp.async.commit_group;" ::: "memory")
#define CP_WAIT(n)  asm volatile("cp.async.wait_group %0;" :: "n"(n) : "memory")

#define LDSM_X4(r0, r1, r2, r3, addr)                                          \
    asm volatile("ldmatrix.sync.aligned.m8n8.x4.shared.b16 {%0,%1,%2,%3}, [%4];" \
        : "=r"(r0), "=r"(r1), "=r"(r2), "=r"(r3) : "r"(addr))
#define LDSM_X2(r0, r1, addr)                                                  \
    asm volatile("ldmatrix.sync.aligned.m8n8.x2.shared.b16 {%0,%1}, [%2];"     \
        : "=r"(r0), "=r"(r1) : "r"(addr))

#define MMA_S8(d, a, b0, b1)                                                   \
    asm volatile("mma.sync.aligned.m16n8k32.row.col.s32.s8.s8.s32 "            \
        "{%0,%1,%2,%3}, {%4,%5,%6,%7}, {%8,%9}, {%0,%1,%2,%3};"                \
        : "+r"((d)[0]), "+r"((d)[1]), "+r"((d)[2]), "+r"((d)[3])               \
        : "r"((a)[0]), "r"((a)[1]), "r"((a)[2]), "r"((a)[3]), "r"(b0), "r"(b1))

#define STS16(addr, v) \
    asm volatile("st.shared.u16 [%0], %1;" :: "r"(addr), "h"((unsigned short)(v)) : "memory")

// quantize pair of activations: a*16256 = a1*128 + a2 (|a|<=1)
__device__ __forceinline__ void quant_pair(float a0, float a1v,
                                           uint32_t& p1, uint32_t& p2) {
    int h0 = __float2int_rn(a0 * 127.0f);
    int h1 = __float2int_rn(a1v * 127.0f);
    int l0 = __float2int_rn(fmaf(a0,  16256.0f, (float)(-(h0 << 7))));
    int l1 = __float2int_rn(fmaf(a1v, 16256.0f, (float)(-(h1 << 7))));
    p1 = (uint32_t)(h0 & 255) | ((uint32_t)(h1 & 255) << 8);
    p2 = (uint32_t)(l0 & 255) | ((uint32_t)(l1 & 255) << 8);
}

// ---------------------------------------------------------------------------
// prep: W1..W4 fp32 [256n,256k] -> int8 w1/w2 planes, k-major rows, k128 chunks
// ---------------------------------------------------------------------------
__global__ void prep_weights(const float* __restrict__ W1, const float* __restrict__ W2,
                             const float* __restrict__ W3, const float* __restrict__ W4) {
    int idx = blockIdx.x * blockDim.x + threadIdx.x;   // 65536
    int kg = idx & 63;                                 // 4-k group
    int n  = (idx >> 6) & 255;
    int l  = idx >> 14;
    const float* W = (l == 0) ? W1 : (l == 1) ? W2 : (l == 2) ? W3 : W4;
    int k0 = kg * 4;
    uint32_t p1 = 0, p2 = 0;
#pragma unroll
    for (int q = 0; q < 4; q++) {
        float w = W[n * 256 + k0 + q];
        int w1 = __float2int_rn(w * 512.0f);                               // |w1| <= 79
        int w2 = __float2int_rn(fmaf(w, 65536.0f, (float)(-(w1 << 7))));   // |w2| <= 64
        p1 |= (uint32_t)(w1 & 255) << (8 * q);
        p2 |= (uint32_t)(w2 & 255) << (8 * q);
    }
    int c  = k0 >> 7;
    int kl = k0 & 127;
    size_t base = (size_t)(l * 2 + c) * W_CHUNK + (size_t)n * W_LDB + (size_t)kl;
    *(uint32_t*)(g_wpacked + base)           = p1;
    *(uint32_t*)(g_wpacked + base + W_PLANE) = p2;
}

// ---------------------------------------------------------------------------
// main kernel
// ---------------------------------------------------------------------------
__device__ __forceinline__ void prefetch_chunk(uint32_t sb, int tid, int g) {
    const char* src = (const char*)g_wpacked + (size_t)g * W_CHUNK + (size_t)tid * 16;
    uint32_t dst = sb + WBUF_OFF + (uint32_t)(g & 1) * W_CHUNK + (uint32_t)tid * 16;
#pragma unroll
    for (int i = 0; i < 18; i++)
        CP_ASYNC16(dst + (uint32_t)i * 4096u, src + (size_t)i * 4096);
    CP_COMMIT();
}

__global__ void __launch_bounds__(THREADS, 1)
siren_i8_kernel(const float* __restrict__ xyt, const float* __restrict__ W0,
                const float* __restrict__ b0, const float* __restrict__ b1,
                const float* __restrict__ b2, const float* __restrict__ b3,
                const float* __restrict__ b4, const float* __restrict__ Wf,
                const float* __restrict__ bfp, float* __restrict__ out) {
    extern __shared__ char smem[];
    const uint32_t sb = smem_u32(smem);
    const int tid  = threadIdx.x;
    const int lane = tid & 31;
    const int wid  = tid >> 5;
    const int mw   = wid & 1;      // 2 warp-groups over M (32 rows each)
    const int ns   = wid >> 1;     // 4 warp-slices over N (64 cols each)
    const int g    = lane >> 2;
    const int t    = lane & 3;

    prefetch_chunk(sb, tid, 0);
    prefetch_chunk(sb, tid, 1);

    float* W0s  = (float*)(smem + W0S_OFF);
    float* b0s  = (float*)(smem + B0S_OFF);
    float* bias = (float*)(smem + BIAS_OFF);
    float* Wfs  = (float*)(smem + WFS_OFF);
    float* red  = (float*)(smem + RED_OFF);
    for (int i = tid; i < 768; i += THREADS) W0s[i] = W0[i];
    if (tid < 256) {
        b0s[tid] = b0[tid];
        bias[tid]       = b1[tid];
        bias[256 + tid] = b2[tid];
        bias[512 + tid] = b3[tid];
        bias[768 + tid] = b4[tid];
        Wfs[tid] = Wf[tid];
    }
    const float bfv = bfp[0];
    __syncthreads();

    // ---- first layer (SIMT): sin(30*(x@W0^T+b0)) -> quantized A planes ----
    {
        int row   = tid >> 2;
        int cbase = (tid & 3) * 64;
        int m = blockIdx.x * M_TILE + row;
        float x0 = xyt[3 * m], x1 = xyt[3 * m + 1], x2 = xyt[3 * m + 2];
        uint32_t abase = sb + AB_OFF + (uint32_t)row * A_LDB + (uint32_t)cbase;
#pragma unroll 4
        for (int q = 0; q < 32; q++) {
            int n = cbase + 2 * q;
            const float* w = W0s + 3 * n;
            float z0 = fmaf(x0, w[0], fmaf(x1, w[1], fmaf(x2, w[2], b0s[n])));
            float z1 = fmaf(x0, w[3], fmaf(x1, w[4], fmaf(x2, w[5], b0s[n + 1])));
            uint32_t p1, p2;
            quant_pair(__sinf(30.0f * z0), __sinf(30.0f * z1), p1, p2);
            STS16(abase + 2 * q, p1);
            STS16(abase + 2 * q + A_PLANE, p2);
        }
    }

    const float C1 = 16384.0f / 1065484288.0f;   // 2^14 / (16256*65536)
    const float C2 = 128.0f   / 1065484288.0f;   // 2^7  / (16256*65536)

    // ---- 4 hidden layers ----
#pragma unroll 1
    for (int l = 0; l < 4; l++) {
        int acc1[2][8][4], acc2[2][8][4];
#pragma unroll
        for (int i = 0; i < 2; i++)
#pragma unroll
            for (int j = 0; j < 8; j++)
#pragma unroll
                for (int e = 0; e < 4; e++) { acc1[i][j][e] = 0; acc2[i][j][e] = 0; }

#pragma unroll 1
        for (int c = 0; c < 2; c++) {
            int gch = l * 2 + c;
            if (gch == 7) { CP_WAIT(0); } else { CP_WAIT(1); }
            __syncthreads();
            uint32_t wb = sb + WBUF_OFF + (uint32_t)(gch & 1) * W_CHUNK;

#pragma unroll
            for (int s = 0; s < 4; s++) {
                int ks = c * 4 + s;
                uint32_t a1f[2][4], a2f[2][4];
#pragma unroll
                for (int i = 0; i < 2; i++) {
                    uint32_t ar = sb + AB_OFF
                        + (uint32_t)((mw * 32 + i * 16 + (lane & 15)) * A_LDB)
                        + (uint32_t)(ks * 32 + (lane >> 4) * 16);
                    LDSM_X4(a1f[i][0], a1f[i][1], a1f[i][2], a1f[i][3], ar);
                    LDSM_X4(a2f[i][0], a2f[i][1], a2f[i][2], a2f[i][3], ar + A_PLANE);
                }
#pragma unroll
                for (int j = 0; j < 8; j++) {
                    uint32_t br = wb
                        + (uint32_t)((ns * 64 + j * 8 + (lane & 7)) * W_LDB)
                        + (uint32_t)(s * 32 + ((lane >> 3) & 1) * 16);
                    uint32_t w1a, w1b, w2a, w2b;
                    LDSM_X2(w1a, w1b, br);
                    LDSM_X2(w2a, w2b, br + W_PLANE);
#pragma unroll
                    for (int i = 0; i < 2; i++) {
                        MMA_S8(acc1[i][j], a1f[i], w1a, w1b);   // a1*w1  -> 2^14
                        MMA_S8(acc2[i][j], a1f[i], w2a, w2b);   // a1*w2  -> 2^7
                        MMA_S8(acc2[i][j], a2f[i], w1a, w1b);   // a2*w1  -> 2^7
                    }
                }
            }
            __syncthreads();
            if (gch + 2 < 8) prefetch_chunk(sb, tid, gch + 2);
        }

        // ---- epilogue ----
        if (l < 3) {
            const float* bs = bias + l * 256;
#pragma unroll
            for (int i = 0; i < 2; i++) {
                int r0 = mw * 32 + i * 16 + g;
                uint32_t ab0 = sb + AB_OFF + (uint32_t)(r0 * A_LDB);
#pragma unroll
                for (int j = 0; j < 8; j++) {
                    int n0 = ns * 64 + j * 8 + 2 * t;
                    float bb0 = bs[n0], bb1 = bs[n0 + 1];
                    float z00 = fmaf((float)acc1[i][j][0], C1,
                                fmaf((float)acc2[i][j][0], C2, bb0));
                    float z01 = fmaf((float)acc1[i][j][1], C1,
                                fmaf((float)acc2[i][j][1], C2, bb1));
                    float z10 = fmaf((float)acc1[i][j][2], C1,
                                fmaf((float)acc2[i][j][2], C2, bb0));
                    float z11 = fmaf((float)acc1[i][j][3], C1,
                                fmaf((float)acc2[i][j][3], C2, bb1));
                    uint32_t p1, p2;
                    quant_pair(__sinf(z00), __sinf(z01), p1, p2);
                    STS16(ab0 + (uint32_t)n0, p1);
                    STS16(ab0 + (uint32_t)n0 + A_PLANE, p2);
                    quant_pair(__sinf(z10), __sinf(z11), p1, p2);
                    STS16(ab0 + 8u * A_LDB + (uint32_t)n0, p1);
                    STS16(ab0 + 8u * A_LDB + (uint32_t)n0 + A_PLANE, p2);
                }
            }
        } else {
            const float* bs = bias + 768;
#pragma unroll
            for (int i = 0; i < 2; i++) {
                float s0 = 0.0f, s1 = 0.0f;
#pragma unroll
                for (int j = 0; j < 8; j++) {
                    int n0 = ns * 64 + j * 8 + 2 * t;
                    float bb0 = bs[n0], bb1 = bs[n0 + 1];
                    float wf0 = Wfs[n0], wf1 = Wfs[n0 + 1];
                    float z00 = fmaf((float)acc1[i][j][0], C1,
                                fmaf((float)acc2[i][j][0], C2, bb0));
                    float z01 = fmaf((float)acc1[i][j][1], C1,
                                fmaf((float)acc2[i][j][1], C2, bb1));
                    float z10 = fmaf((float)acc1[i][j][2], C1,
                                fmaf((float)acc2[i][j][2], C2, bb0));
                    float z11 = fmaf((float)acc1[i][j][3], C1,
                                fmaf((float)acc2[i][j][3], C2, bb1));
                    s0 = fmaf(__sinf(z00), wf0, s0);
                    s0 = fmaf(__sinf(z01), wf1, s0);
                    s1 = fmaf(__sinf(z10), wf0, s1);
                    s1 = fmaf(__sinf(z11), wf1, s1);
                }
                s0 += __shfl_xor_sync(0xffffffffu, s0, 1);
                s0 += __shfl_xor_sync(0xffffffffu, s0, 2);
                s1 += __shfl_xor_sync(0xffffffffu, s1, 1);
                s1 += __shfl_xor_sync(0xffffffffu, s1, 2);
                if (t == 0) {
                    int r0 = mw * 32 + i * 16 + g;
                    red[r0 * 4 + ns]       = s0;
                    red[(r0 + 8) * 4 + ns] = s1;
                }
            }
            __syncthreads();
            if (tid < 64) {
                float s = red[tid * 4] + red[tid * 4 + 1] +
                          red[tid * 4 + 2] + red[tid * 4 + 3] + bfv;
                out[(size_t)blockIdx.x * M_TILE + tid] = s;
            }
        }
    }
}

// ---------------------------------------------------------------------------
// kernel_launch
// ---------------------------------------------------------------------------
extern "C" void kernel_launch(void* const* d_in, const int* in_sizes, int n_in,
                              void* d_out, int out_size) {
    const float* xyt = (const float*)d_in[0];
    const float* W0  = (const float*)d_in[1];
    const float* b0  = (const float*)d_in[2];
    const float* W1  = (const float*)d_in[3];
    const float* b1  = (const float*)d_in[4];
    const float* W2  = (const float*)d_in[5];
    const float* b2  = (const float*)d_in[6];
    const float* W3  = (const float*)d_in[7];
    const float* b3  = (const float*)d_in[8];
    const float* W4  = (const float*)d_in[9];
    const float* b4  = (const float*)d_in[10];
    const float* Wf  = (const float*)d_in[11];
    const float* bf  = (const float*)d_in[12];
    float* out = (float*)d_out;
    (void)in_sizes; (void)n_in; (void)out_size;

    cudaFuncSetAttribute(siren_i8_kernel,
                         cudaFuncAttributeMaxDynamicSharedMemorySize, SMEM_TOTAL);

    prep_weights<<<256, 256>>>(W1, W2, W3, W4);
    siren_i8_kernel<<<GRID_CTAS, THREADS, SMEM_TOTAL>>>(
        xyt, W0, b0, b1, b2, b3, b4, Wf, bf, out);
}

// round 6
// speedup vs baseline: 6.8701x; 6.8701x over previous
#include <cuda_runtime.h>
#include <cuda_fp16.h>
#include <cstdint>

// ============================================================================
// SIREN fused inference via fp16 mma.sync m16n8k16 (sm_103-safe PTX).
// Activations split exactly into fp16 hi + fp16 lo (residual <= 2^-22);
// weights rounded once to fp16 (error ~1.4e-4 rms -> output ~2e-4).
// z = a_hi @ W + a_lo @ W : 2 MMAs per k16 (vs 3 in the bf16 3-term split).
// Bulk-synchronous layers; W fp16-packed, streamed L2->SMEM via cp.async
// (k64 double-buffered chunks); ldmatrix broadcast from SMEM.
// ============================================================================

#define THREADS    256
#define M_TILE     128
#define N_POINTS   1048576
#define GRID_CTAS  (N_POINTS / M_TILE)      // 8192

// --- SMEM layout (bytes) ---
#define A_LDB      528                       // 264 halves per row (16B pad)
#define A_PLANE    (128 * A_LDB)             // 67584 (planes: hi, lo)
#define AB_OFF     0
#define WBUF_OFF   (2 * A_PLANE)             // 135168
#define W_LDB      144                       // 64 k halves (128B) + 16 pad
#define W_CHUNK    (256 * W_LDB)             // 36864 (k64 chunk, single plane)
#define W0S_OFF    (WBUF_OFF + 2 * W_CHUNK)  // 208896
#define B0S_OFF    (W0S_OFF + 3072)
#define BIAS_OFF   (B0S_OFF + 1024)
#define WFS_OFF    (BIAS_OFF + 4096)
#define RED_OFF    (WFS_OFF + 1024)
#define SMEM_TOTAL (RED_OFF + 2048)          // 220160

// fp16-packed weights: 16 chunks (layer*4 + kc), each 36864B
__device__ __align__(128) unsigned char g_wpacked[16 * W_CHUNK];

// ---------------------------------------------------------------------------
// helpers
// ---------------------------------------------------------------------------
__device__ __forceinline__ uint32_t smem_u32(const void* p) {
    uint32_t a;
    asm("{ .reg .u64 t; cvta.to.shared.u64 t, %1; cvt.u32.u64 %0, t; }"
        : "=r"(a) : "l"(p));
    return a;
}

#define CP_ASYNC16(dst, src) \
    asm volatile("cp.async.cg.shared.global [%0], [%1], 16;" :: "r"(dst), "l"(src) : "memory")
#define CP_COMMIT() asm volatile("cp.async.commit_group;" ::: "memory")
#define CP_WAIT(n)  asm volatile("cp.async.wait_group %0;" :: "n"(n) : "memory")

#define LDSM_X4(r0, r1, r2, r3, addr)                                          \
    asm volatile("ldmatrix.sync.aligned.m8n8.x4.shared.b16 {%0,%1,%2,%3}, [%4];" \
        : "=r"(r0), "=r"(r1), "=r"(r2), "=r"(r3) : "r"(addr))

#define MMA_F16(d, a0, a1, a2, a3, b0, b1)                                     \
    asm volatile("mma.sync.aligned.m16n8k16.row.col.f32.f16.f16.f32 "          \
        "{%0,%1,%2,%3}, {%4,%5,%6,%7}, {%8,%9}, {%0,%1,%2,%3};"                \
        : "+f"((d)[0]), "+f"((d)[1]), "+f"((d)[2]), "+f"((d)[3])               \
        : "r"(a0), "r"(a1), "r"(a2), "r"(a3), "r"(b0), "r"(b1))

// exact fp16 split of two fp32: hw = {h(z0), h(z1)}, lw = {h(res0), h(res1)}
__device__ __forceinline__ void split_pack_f16(float z0, float z1,
                                               uint32_t& hw, uint32_t& lw) {
    __half h0 = __float2half_rn(z0);
    __half h1 = __float2half_rn(z1);
    float r0 = z0 - __half2float(h0);
    float r1 = z1 - __half2float(h1);
    __half2 hp = __halves2half2(h0, h1);
    __half2 lp = __halves2half2(__float2half_rn(r0), __float2half_rn(r1));
    hw = *(uint32_t*)&hp;
    lw = *(uint32_t*)&lp;
}

// ---------------------------------------------------------------------------
// prep: W1..W4 fp32 [256n,256k] -> fp16, k-major rows of 64 k + pad, 16 chunks
// ---------------------------------------------------------------------------
__global__ void prep_weights(const float* __restrict__ W1, const float* __restrict__ W2,
                             const float* __restrict__ W3, const float* __restrict__ W4) {
    int idx = blockIdx.x * blockDim.x + threadIdx.x;   // 65536
    int kg = idx & 63;                                 // 4-k group within 256
    int n  = (idx >> 6) & 255;
    int l  = idx >> 14;
    const float* W = (l == 0) ? W1 : (l == 1) ? W2 : (l == 2) ? W3 : W4;
    int k0 = kg * 4;
    __half2 p01 = __halves2half2(__float2half_rn(W[n * 256 + k0]),
                                 __float2half_rn(W[n * 256 + k0 + 1]));
    __half2 p23 = __halves2half2(__float2half_rn(W[n * 256 + k0 + 2]),
                                 __float2half_rn(W[n * 256 + k0 + 3]));
    int kc = k0 >> 6;                                  // chunk within layer
    int kl = k0 & 63;                                  // k within chunk
    size_t base = (size_t)(l * 4 + kc) * W_CHUNK + (size_t)n * W_LDB + (size_t)kl * 2;
    *(uint2*)(g_wpacked + base) = make_uint2(*(uint32_t*)&p01, *(uint32_t*)&p23);
}

// ---------------------------------------------------------------------------
// main kernel
// ---------------------------------------------------------------------------
__device__ __forceinline__ void prefetch_chunk(uint32_t sb, int tid, int g) {
    const char* src = (const char*)g_wpacked + (size_t)g * W_CHUNK + (size_t)tid * 16;
    uint32_t dst = sb + WBUF_OFF + (uint32_t)(g & 1) * W_CHUNK + (uint32_t)tid * 16;
#pragma unroll
    for (int i = 0; i < 9; i++)
        CP_ASYNC16(dst + (uint32_t)i * 4096u, src + (size_t)i * 4096);
    CP_COMMIT();
}

__global__ void __launch_bounds__(THREADS, 1)
siren_f16_kernel(const float* __restrict__ xyt, const float* __restrict__ W0,
                 const float* __restrict__ b0, const float* __restrict__ b1,
                 const float* __restrict__ b2, const float* __restrict__ b3,
                 const float* __restrict__ b4, const float* __restrict__ Wf,
                 const float* __restrict__ bfp, float* __restrict__ out) {
    extern __shared__ char smem[];
    const uint32_t sb = smem_u32(smem);
    const int tid = threadIdx.x;
    const int lane = tid & 31;
    const int wid = tid >> 5;
    const int warp_m = wid & 1;    // 2 warps over M (64 rows each)
    const int warp_n = wid >> 1;   // 4 warps over N (64 cols each)

    prefetch_chunk(sb, tid, 0);
    prefetch_chunk(sb, tid, 1);

    float* W0s  = (float*)(smem + W0S_OFF);
    float* b0s  = (float*)(smem + B0S_OFF);
    float* bias = (float*)(smem + BIAS_OFF);
    float* Wfs  = (float*)(smem + WFS_OFF);
    for (int i = tid; i < 768; i += THREADS) W0s[i] = W0[i];
    if (tid < 256) {
        b0s[tid] = b0[tid];
        bias[tid]       = b1[tid];
        bias[256 + tid] = b2[tid];
        bias[512 + tid] = b3[tid];
        bias[768 + tid] = b4[tid];
        Wfs[tid] = Wf[tid];
    }
    __syncthreads();

    // ---- first layer (SIMT): sin(30*(x@W0^T+b0)) -> A hi/lo planes ----
    {
        int p = tid & 127;
        int half = tid >> 7;           // two threads per point, 128 n each
        int m = blockIdx.x * M_TILE + p;
        float x0 = xyt[3 * m], x1 = xyt[3 * m + 1], x2 = xyt[3 * m + 2];
        char* arow = smem + (uint32_t)p * A_LDB + (uint32_t)half * 256;
#pragma unroll 4
        for (int q = 0; q < 64; q++) {
            int n = half * 128 + 2 * q;
            float z0 = fmaf(x0, W0s[3*n+0], fmaf(x1, W0s[3*n+1], fmaf(x2, W0s[3*n+2], b0s[n])));
            float z1 = fmaf(x0, W0s[3*n+3], fmaf(x1, W0s[3*n+4], fmaf(x2, W0s[3*n+5], b0s[n+1])));
            uint32_t hw, lw;
            split_pack_f16(__sinf(30.0f * z0), __sinf(30.0f * z1), hw, lw);
            *(uint32_t*)(arow + 4 * q)           = hw;
            *(uint32_t*)(arow + A_PLANE + 4 * q) = lw;
        }
    }
    // (first chunk-iteration __syncthreads gates A visibility)

    // ---- 4 hidden layers ----
#pragma unroll 1
    for (int layer = 0; layer < 4; layer++) {
        float acc[4][8][4];
#pragma unroll
        for (int i = 0; i < 4; i++)
#pragma unroll
            for (int j = 0; j < 8; j++)
#pragma unroll
                for (int e = 0; e < 4; e++) acc[i][j][e] = 0.0f;

#pragma unroll 1
        for (int kc = 0; kc < 4; kc++) {
            int g = layer * 4 + kc;
            if (g == 15) { CP_WAIT(0); } else { CP_WAIT(1); }
            __syncthreads();
            uint32_t wb = sb + WBUF_OFF + (uint32_t)(g & 1) * W_CHUNK;

#pragma unroll
            for (int ks = 0; ks < 4; ks++) {
                // B fragments: 4 x4-ldsm, each covering 2 n8-tiles x k16
                uint32_t bh[4][4];
#pragma unroll
                for (int jj = 0; jj < 4; jj++) {
                    uint32_t baddr = wb
                        + (uint32_t)((warp_n * 64 + jj * 16 + (lane & 7) + ((lane >> 4) * 8)) * W_LDB)
                        + (uint32_t)(ks * 32 + ((lane >> 3) & 1) * 16);
                    LDSM_X4(bh[jj][0], bh[jj][1], bh[jj][2], bh[jj][3], baddr);
                }
#pragma unroll
                for (int i = 0; i < 4; i++) {
                    uint32_t aaddr = sb
                        + (uint32_t)((warp_m * 64 + i * 16 + (lane & 15)) * A_LDB)
                        + (uint32_t)((kc * 4 + ks) * 32 + (lane >> 4) * 16);
                    uint32_t ah0, ah1, ah2, ah3, al0, al1, al2, al3;
                    LDSM_X4(ah0, ah1, ah2, ah3, aaddr);
                    LDSM_X4(al0, al1, al2, al3, aaddr + A_PLANE);
#pragma unroll
                    for (int j = 0; j < 8; j++) {
                        uint32_t b0 = bh[j >> 1][(j & 1) * 2];
                        uint32_t b1 = bh[j >> 1][(j & 1) * 2 + 1];
                        MMA_F16(acc[i][j], ah0, ah1, ah2, ah3, b0, b1);  // hi*w
                        MMA_F16(acc[i][j], al0, al1, al2, al3, b0, b1);  // lo*w
                    }
                }
            }
            __syncthreads();
            if (g + 2 < 16) prefetch_chunk(sb, tid, g + 2);
        }

        // ---- epilogue ----
        if (layer < 3) {
            const float* bs = bias + layer * 256;
#pragma unroll
            for (int i = 0; i < 4; i++) {
                int r0 = warp_m * 64 + i * 16 + (lane >> 2);
#pragma unroll
                for (int j = 0; j < 8; j++) {
                    int n0 = warp_n * 64 + j * 8 + (lane & 3) * 2;
                    uint32_t off = (uint32_t)(r0 * A_LDB + n0 * 2);
                    uint32_t hw, lw;
                    float z0 = acc[i][j][0] + bs[n0];
                    float z1 = acc[i][j][1] + bs[n0 + 1];
                    split_pack_f16(__sinf(z0), __sinf(z1), hw, lw);
                    *(uint32_t*)(smem + off)           = hw;
                    *(uint32_t*)(smem + A_PLANE + off) = lw;
                    z0 = acc[i][j][2] + bs[n0];
                    z1 = acc[i][j][3] + bs[n0 + 1];
                    split_pack_f16(__sinf(z0), __sinf(z1), hw, lw);
                    off += 8u * A_LDB;
                    *(uint32_t*)(smem + off)           = hw;
                    *(uint32_t*)(smem + A_PLANE + off) = lw;
                }
            }
            // next iteration's post-CP_WAIT __syncthreads gates these writes
        } else {
            // final: out[m] = sum_n sin(z[m,n]) * Wf[n] + bf
            const float* bs = bias + 768;
            float* red = (float*)(smem + RED_OFF);
#pragma unroll
            for (int i = 0; i < 4; i++) {
                float p0 = 0.0f, p1 = 0.0f;
#pragma unroll
                for (int j = 0; j < 8; j++) {
                    int n0 = warp_n * 64 + j * 8 + (lane & 3) * 2;
                    p0 = fmaf(__sinf(acc[i][j][0] + bs[n0]),     Wfs[n0],     p0);
                    p0 = fmaf(__sinf(acc[i][j][1] + bs[n0 + 1]), Wfs[n0 + 1], p0);
                    p1 = fmaf(__sinf(acc[i][j][2] + bs[n0]),     Wfs[n0],     p1);
                    p1 = fmaf(__sinf(acc[i][j][3] + bs[n0 + 1]), Wfs[n0 + 1], p1);
                }
                p0 += __shfl_xor_sync(0xffffffffu, p0, 1);
                p0 += __shfl_xor_sync(0xffffffffu, p0, 2);
                p1 += __shfl_xor_sync(0xffffffffu, p1, 1);
                p1 += __shfl_xor_sync(0xffffffffu, p1, 2);
                if ((lane & 3) == 0) {
                    int r0 = warp_m * 64 + i * 16 + (lane >> 2);
                    red[r0 * 4 + warp_n]       = p0;
                    red[(r0 + 8) * 4 + warp_n] = p1;
                }
            }
            __syncthreads();
            if (tid < 128) {
                float s = red[tid * 4] + red[tid * 4 + 1] +
                          red[tid * 4 + 2] + red[tid * 4 + 3] + bfp[0];
                out[(size_t)blockIdx.x * M_TILE + tid] = s;
            }
        }
    }
}

// ---------------------------------------------------------------------------
// kernel_launch
// ---------------------------------------------------------------------------
extern "C" void kernel_launch(void* const* d_in, const int* in_sizes, int n_in,
                              void* d_out, int out_size) {
    const float* xyt = (const float*)d_in[0];
    const float* W0  = (const float*)d_in[1];
    const float* b0  = (const float*)d_in[2];
    const float* W1  = (const float*)d_in[3];
    const float* b1  = (const float*)d_in[4];
    const float* W2  = (const float*)d_in[5];
    const float* b2  = (const float*)d_in[6];
    const float* W3  = (const float*)d_in[7];
    const float* b3  = (const float*)d_in[8];
    const float* W4  = (const float*)d_in[9];
    const float* b4  = (const float*)d_in[10];
    const float* Wf  = (const float*)d_in[11];
    const float* bf  = (const float*)d_in[12];
    float* out = (float*)d_out;
    (void)in_sizes; (void)n_in; (void)out_size;

    cudaFuncSetAttribute(siren_f16_kernel,
                         cudaFuncAttributeMaxDynamicSharedMemorySize, SMEM_TOTAL);

    prep_weights<<<256, 256>>>(W1, W2, W3, W4);
    siren_f16_kernel<<<GRID_CTAS, THREADS, SMEM_TOTAL>>>(
        xyt, W0, b0, b1, b2, b3, b4, Wf, bf, out);
}

// round 7
// speedup vs baseline: 6.9719x; 1.0148x over previous
#include <cuda_runtime.h>
#include <cuda_fp16.h>
#include <cstdint>

// ============================================================================
// SIREN fused inference via fp16 mma.sync m16n8k16 (sm_103-safe PTX).
// R6: M_TILE=64, SMEM=114688 -> 2 CTAs/SM so one CTA's epilogue/barriers
// overlap the other's HMMAs. Numerics identical to R5 (exact fp16 hi/lo
// activation split x fp16 weights, 2 MMAs per k16).
// ============================================================================

#define THREADS    256
#define M_TILE     64
#define N_POINTS   1048576
#define GRID_CTAS  (N_POINTS / M_TILE)      // 16384

// --- SMEM layout (bytes) ---
#define A_LDB      528                       // 256 k halves + 16B pad
#define A_PLANE    (64 * A_LDB)              // 33792 (planes: hi, lo)
#define AB_OFF     0
#define WBUF_OFF   (2 * A_PLANE)             // 67584
#define W_LDB      80                        // 32 k halves (64B) + 16B pad
#define W_CHUNK    (256 * W_LDB)             // 20480 (k32 chunk)
#define BIAS_OFF   (WBUF_OFF + 2 * W_CHUNK)  // 108544 : b0..b4 (5*256 f32)
#define WFS_OFF    (BIAS_OFF + 5120)         // 113664 : Wf (256 f32)
#define SMEM_TOTAL (WFS_OFF + 1024)          // 114688 = 14*8192 exactly
// red buffer for final reduction reuses the A area (A dead by then)

// fp16-packed weights: 32 chunks (layer*8 + kc), each 20480B
__device__ __align__(128) unsigned char g_wpacked[32 * W_CHUNK];

// ---------------------------------------------------------------------------
// helpers
// ---------------------------------------------------------------------------
__device__ __forceinline__ uint32_t smem_u32(const void* p) {
    uint32_t a;
    asm("{ .reg .u64 t; cvta.to.shared.u64 t, %1; cvt.u32.u64 %0, t; }"
        : "=r"(a) : "l"(p));
    return a;
}

#define CP_ASYNC16(dst, src) \
    asm volatile("cp.async.cg.shared.global [%0], [%1], 16;" :: "r"(dst), "l"(src) : "memory")
#define CP_COMMIT() asm volatile("cp.async.commit_group;" ::: "memory")
#define CP_WAIT(n)  asm volatile("cp.async.wait_group %0;" :: "n"(n) : "memory")

#define LDSM_X4(r0, r1, r2, r3, addr)                                          \
    asm volatile("ldmatrix.sync.aligned.m8n8.x4.shared.b16 {%0,%1,%2,%3}, [%4];" \
        : "=r"(r0), "=r"(r1), "=r"(r2), "=r"(r3) : "r"(addr))

#define MMA_F16(d, a0, a1, a2, a3, b0, b1)                                     \
    asm volatile("mma.sync.aligned.m16n8k16.row.col.f32.f16.f16.f32 "          \
        "{%0,%1,%2,%3}, {%4,%5,%6,%7}, {%8,%9}, {%0,%1,%2,%3};"                \
        : "+f"((d)[0]), "+f"((d)[1]), "+f"((d)[2]), "+f"((d)[3])               \
        : "r"(a0), "r"(a1), "r"(a2), "r"(a3), "r"(b0), "r"(b1))

// exact fp16 split of two fp32
__device__ __forceinline__ void split_pack_f16(float z0, float z1,
                                               uint32_t& hw, uint32_t& lw) {
    __half h0 = __float2half_rn(z0);
    __half h1 = __float2half_rn(z1);
    float r0 = z0 - __half2float(h0);
    float r1 = z1 - __half2float(h1);
    __half2 hp = __halves2half2(h0, h1);
    __half2 lp = __halves2half2(__float2half_rn(r0), __float2half_rn(r1));
    hw = *(uint32_t*)&hp;
    lw = *(uint32_t*)&lp;
}

// ---------------------------------------------------------------------------
// prep: W1..W4 fp32 [256n,256k] -> fp16 k32 chunks, 80B padded rows
// ---------------------------------------------------------------------------
__global__ void prep_weights(const float* __restrict__ W1, const float* __restrict__ W2,
                             const float* __restrict__ W3, const float* __restrict__ W4) {
    int idx = blockIdx.x * blockDim.x + threadIdx.x;   // 65536
    int grp = idx & 7;                                 // 4-half group in row
    int n   = (idx >> 3) & 255;
    int kc  = (idx >> 11) & 7;                         // k32 chunk in layer
    int l   = idx >> 14;
    const float* W = (l == 0) ? W1 : (l == 1) ? W2 : (l == 2) ? W3 : W4;
    int k0 = kc * 32 + grp * 4;
    __half2 p01 = __halves2half2(__float2half_rn(W[n * 256 + k0]),
                                 __float2half_rn(W[n * 256 + k0 + 1]));
    __half2 p23 = __halves2half2(__float2half_rn(W[n * 256 + k0 + 2]),
                                 __float2half_rn(W[n * 256 + k0 + 3]));
    size_t base = (size_t)(l * 8 + kc) * W_CHUNK + (size_t)n * W_LDB + (size_t)grp * 8;
    *(uint2*)(g_wpacked + base) = make_uint2(*(uint32_t*)&p01, *(uint32_t*)&p23);
}

// ---------------------------------------------------------------------------
// main kernel
// ---------------------------------------------------------------------------
__device__ __forceinline__ void prefetch_chunk(uint32_t sb, int tid, int g) {
    const char* src = (const char*)g_wpacked + (size_t)g * W_CHUNK + (size_t)tid * 16;
    uint32_t dst = sb + WBUF_OFF + (uint32_t)(g & 1) * W_CHUNK + (uint32_t)tid * 16;
#pragma unroll
    for (int i = 0; i < 5; i++)
        CP_ASYNC16(dst + (uint32_t)i * 4096u, src + (size_t)i * 4096);
    CP_COMMIT();
}

__global__ void __launch_bounds__(THREADS, 2)
siren_f16_kernel(const float* __restrict__ xyt, const float* __restrict__ W0,
                 const float* __restrict__ b0, const float* __restrict__ b1,
                 const float* __restrict__ b2, const float* __restrict__ b3,
                 const float* __restrict__ b4, const float* __restrict__ Wf,
                 const float* __restrict__ bfp, float* __restrict__ out) {
    extern __shared__ char smem[];
    const uint32_t sb = smem_u32(smem);
    const int tid = threadIdx.x;
    const int lane = tid & 31;
    const int wid = tid >> 5;
    const int warp_m = wid & 1;    // 2 warp-rows over M (32 rows each)
    const int warp_n = wid >> 1;   // 4 warp-slices over N (64 cols each)

    prefetch_chunk(sb, tid, 0);
    prefetch_chunk(sb, tid, 1);

    float* bias = (float*)(smem + BIAS_OFF);   // b0..b4
    float* Wfs  = (float*)(smem + WFS_OFF);
    if (tid < 256) {
        bias[tid]        = b0[tid];
        bias[256 + tid]  = b1[tid];
        bias[512 + tid]  = b2[tid];
        bias[768 + tid]  = b3[tid];
        bias[1024 + tid] = b4[tid];
        Wfs[tid] = Wf[tid];
    }
    __syncthreads();

    // ---- first layer (SIMT): sin(30*(x@W0^T+b0)) -> A hi/lo planes ----
    {
        int row   = tid >> 2;                  // 0..63
        int cbase = (tid & 3) * 64;            // 64 n-cols per thread
        int m = blockIdx.x * M_TILE + row;
        float x0 = __ldg(&xyt[3 * m]), x1 = __ldg(&xyt[3 * m + 1]), x2 = __ldg(&xyt[3 * m + 2]);
        char* arow = smem + (uint32_t)row * A_LDB + (uint32_t)cbase * 2;
#pragma unroll 4
        for (int q = 0; q < 32; q++) {
            int n = cbase + 2 * q;
            const float* w = W0 + 3 * n;
            float z0 = fmaf(x0, __ldg(w),     fmaf(x1, __ldg(w + 1), fmaf(x2, __ldg(w + 2), bias[n])));
            float z1 = fmaf(x0, __ldg(w + 3), fmaf(x1, __ldg(w + 4), fmaf(x2, __ldg(w + 5), bias[n + 1])));
            uint32_t hw, lw;
            split_pack_f16(__sinf(30.0f * z0), __sinf(30.0f * z1), hw, lw);
            *(uint32_t*)(arow + 4 * q)           = hw;
            *(uint32_t*)(arow + A_PLANE + 4 * q) = lw;
        }
    }
    // (first chunk-iteration __syncthreads gates A visibility)

    // ---- 4 hidden layers ----
#pragma unroll 1
    for (int layer = 0; layer < 4; layer++) {
        float acc[2][8][4];
#pragma unroll
        for (int i = 0; i < 2; i++)
#pragma unroll
            for (int j = 0; j < 8; j++)
#pragma unroll
                for (int e = 0; e < 4; e++) acc[i][j][e] = 0.0f;

#pragma unroll 1
        for (int kc = 0; kc < 8; kc++) {
            int g = layer * 8 + kc;
            if (g == 31) { CP_WAIT(0); } else { CP_WAIT(1); }
            __syncthreads();
            uint32_t wb = sb + WBUF_OFF + (uint32_t)(g & 1) * W_CHUNK;

#pragma unroll
            for (int ks = 0; ks < 2; ks++) {
                // B fragments: 4 x4-ldsm, each covering 16 n-rows x k16
                uint32_t bh[4][4];
#pragma unroll
                for (int jj = 0; jj < 4; jj++) {
                    uint32_t baddr = wb
                        + (uint32_t)((warp_n * 64 + jj * 16 + (lane & 7) + ((lane >> 4) * 8)) * W_LDB)
                        + (uint32_t)(ks * 32 + ((lane >> 3) & 1) * 16);
                    LDSM_X4(bh[jj][0], bh[jj][1], bh[jj][2], bh[jj][3], baddr);
                }
#pragma unroll
                for (int i = 0; i < 2; i++) {
                    uint32_t aaddr = sb
                        + (uint32_t)((warp_m * 32 + i * 16 + (lane & 15)) * A_LDB)
                        + (uint32_t)((kc * 2 + ks) * 32 + (lane >> 4) * 16);
                    uint32_t ah0, ah1, ah2, ah3, al0, al1, al2, al3;
                    LDSM_X4(ah0, ah1, ah2, ah3, aaddr);
                    LDSM_X4(al0, al1, al2, al3, aaddr + A_PLANE);
#pragma unroll
                    for (int j = 0; j < 8; j++) {
                        uint32_t b0r = bh[j >> 1][(j & 1) * 2];
                        uint32_t b1r = bh[j >> 1][(j & 1) * 2 + 1];
                        MMA_F16(acc[i][j], ah0, ah1, ah2, ah3, b0r, b1r);  // hi*w
                        MMA_F16(acc[i][j], al0, al1, al2, al3, b0r, b1r);  // lo*w
                    }
                }
            }
            __syncthreads();
            if (g + 2 < 32) prefetch_chunk(sb, tid, g + 2);
        }

        // ---- epilogue ----
        if (layer < 3) {
            const float* bs = bias + (layer + 1) * 256;
#pragma unroll
            for (int i = 0; i < 2; i++) {
                int r0 = warp_m * 32 + i * 16 + (lane >> 2);
#pragma unroll
                for (int j = 0; j < 8; j++) {
                    int n0 = warp_n * 64 + j * 8 + (lane & 3) * 2;
                    uint32_t off = (uint32_t)(r0 * A_LDB + n0 * 2);
                    uint32_t hw, lw;
                    float z0 = acc[i][j][0] + bs[n0];
                    float z1 = acc[i][j][1] + bs[n0 + 1];
                    split_pack_f16(__sinf(z0), __sinf(z1), hw, lw);
                    *(uint32_t*)(smem + off)           = hw;
                    *(uint32_t*)(smem + A_PLANE + off) = lw;
                    z0 = acc[i][j][2] + bs[n0];
                    z1 = acc[i][j][3] + bs[n0 + 1];
                    split_pack_f16(__sinf(z0), __sinf(z1), hw, lw);
                    off += 8u * A_LDB;
                    *(uint32_t*)(smem + off)           = hw;
                    *(uint32_t*)(smem + A_PLANE + off) = lw;
                }
            }
            // next iteration's post-CP_WAIT __syncthreads gates these writes
        } else {
            // final: out[m] = sum_n sin(z[m,n]) * Wf[n] + bf
            const float* bs = bias + 1024;
            float* red = (float*)(smem + AB_OFF);   // reuse dead A area
#pragma unroll
            for (int i = 0; i < 2; i++) {
                float p0 = 0.0f, p1 = 0.0f;
#pragma unroll
                for (int j = 0; j < 8; j++) {
                    int n0 = warp_n * 64 + j * 8 + (lane & 3) * 2;
                    p0 = fmaf(__sinf(acc[i][j][0] + bs[n0]),     Wfs[n0],     p0);
                    p0 = fmaf(__sinf(acc[i][j][1] + bs[n0 + 1]), Wfs[n0 + 1], p0);
                    p1 = fmaf(__sinf(acc[i][j][2] + bs[n0]),     Wfs[n0],     p1);
                    p1 = fmaf(__sinf(acc[i][j][3] + bs[n0 + 1]), Wfs[n0 + 1], p1);
                }
                p0 += __shfl_xor_sync(0xffffffffu, p0, 1);
                p0 += __shfl_xor_sync(0xffffffffu, p0, 2);
                p1 += __shfl_xor_sync(0xffffffffu, p1, 1);
                p1 += __shfl_xor_sync(0xffffffffu, p1, 2);
                if ((lane & 3) == 0) {
                    int r0 = warp_m * 32 + i * 16 + (lane >> 2);
                    red[r0 * 4 + warp_n]       = p0;
                    red[(r0 + 8) * 4 + warp_n] = p1;
                }
            }
            __syncthreads();
            if (tid < 64) {
                float s = red[tid * 4] + red[tid * 4 + 1] +
                          red[tid * 4 + 2] + red[tid * 4 + 3] + bfp[0];
                out[(size_t)blockIdx.x * M_TILE + tid] = s;
            }
        }
    }
}

// ---------------------------------------------------------------------------
// kernel_launch
// ---------------------------------------------------------------------------
extern "C" void kernel_launch(void* const* d_in, const int* in_sizes, int n_in,
                              void* d_out, int out_size) {
    const float* xyt = (const float*)d_in[0];
    const float* W0  = (const float*)d_in[1];
    const float* b0  = (const float*)d_in[2];
    const float* W1  = (const float*)d_in[3];
    const float* b1  = (const float*)d_in[4];
    const float* W2  = (const float*)d_in[5];
    const float* b2  = (const float*)d_in[6];
    const float* W3  = (const float*)d_in[7];
    const float* b3  = (const float*)d_in[8];
    const float* W4  = (const float*)d_in[9];
    const float* b4  = (const float*)d_in[10];
    const float* Wf  = (const float*)d_in[11];
    const float* bf  = (const float*)d_in[12];
    float* out = (float*)d_out;
    (void)in_sizes; (void)n_in; (void)out_size;

    cudaFuncSetAttribute(siren_f16_kernel,
                         cudaFuncAttributeMaxDynamicSharedMemorySize, SMEM_TOTAL);

    prep_weights<<<256, 256>>>(W1, W2, W3, W4);
    siren_f16_kernel<<<GRID_CTAS, THREADS, SMEM_TOTAL>>>(
        xyt, W0, b0, b1, b2, b3, b4, Wf, bf, out);
}

// round 9
// speedup vs baseline: 9.6679x; 1.3867x over previous
#include <cuda_runtime.h>
#include <cuda_fp16.h>
#include <cstdint>

// ============================================================================
// SIREN fused inference via fp16 mma.sync m16n8k16 (sm_103-safe PTX).
// R8 = R7 + fixed weight-prefetch chain in the layer-4 loop (R7 never
// prefetched chunks 26..31 -> layer 4 consumed stale SMEM, rel_err 1.26).
// Layers 1-3: single-fp16 activations (1 MMA/k16). Layer 4: exact fp16
// hi/lo activation split (2 MMAs/k16). Weights fp16. 2 CTAs/SM.
// ============================================================================

#define THREADS    256
#define M_TILE     64
#define N_POINTS   1048576
#define GRID_CTAS  (N_POINTS / M_TILE)      // 16384

// --- SMEM layout (bytes) ---
#define A_LDB      528                       // 256 k halves + 16B pad
#define A_PLANE    (64 * A_LDB)              // 33792 (planes: hi, lo)
#define AB_OFF     0
#define WBUF_OFF   (2 * A_PLANE)             // 67584
#define W_LDB      80                        // 32 k halves (64B) + 16B pad
#define W_CHUNK    (256 * W_LDB)             // 20480 (k32 chunk)
#define BIAS_OFF   (WBUF_OFF + 2 * W_CHUNK)  // 108544 : b0..b4 (5*256 f32)
#define WFS_OFF    (BIAS_OFF + 5120)         // 113664 : Wf (256 f32)
#define SMEM_TOTAL (WFS_OFF + 1024)          // 114688 -> 2 CTAs/SM
// final-reduction buffer reuses the (dead) A area

// fp16-packed weights: 32 chunks (layer*8 + kc), each 20480B
__device__ __align__(128) unsigned char g_wpacked[32 * W_CHUNK];

// ---------------------------------------------------------------------------
// helpers
// ---------------------------------------------------------------------------
__device__ __forceinline__ uint32_t smem_u32(const void* p) {
    uint32_t a;
    asm("{ .reg .u64 t; cvta.to.shared.u64 t, %1; cvt.u32.u64 %0, t; }"
        : "=r"(a) : "l"(p));
    return a;
}

#define CP_ASYNC16(dst, src) \
    asm volatile("cp.async.cg.shared.global [%0], [%1], 16;" :: "r"(dst), "l"(src) : "memory")
#define CP_COMMIT() asm volatile("cp.async.commit_group;" ::: "memory")
#define CP_WAIT(n)  asm volatile("cp.async.wait_group %0;" :: "n"(n) : "memory")

#define LDSM_X4(r0, r1, r2, r3, addr)                                          \
    asm volatile("ldmatrix.sync.aligned.m8n8.x4.shared.b16 {%0,%1,%2,%3}, [%4];" \
        : "=r"(r0), "=r"(r1), "=r"(r2), "=r"(r3) : "r"(addr))

#define MMA_F16(d, a0, a1, a2, a3, b0, b1)                                     \
    asm volatile("mma.sync.aligned.m16n8k16.row.col.f32.f16.f16.f32 "          \
        "{%0,%1,%2,%3}, {%4,%5,%6,%7}, {%8,%9}, {%0,%1,%2,%3};"                \
        : "+f"((d)[0]), "+f"((d)[1]), "+f"((d)[2]), "+f"((d)[3])               \
        : "r"(a0), "r"(a1), "r"(a2), "r"(a3), "r"(b0), "r"(b1))

// single fp16 pack of two fp32
__device__ __forceinline__ uint32_t pack_f16(float z0, float z1) {
    __half2 hp = __halves2half2(__float2half_rn(z0), __float2half_rn(z1));
    return *(uint32_t*)&hp;
}
// exact fp16 split of two fp32
__device__ __forceinline__ void split_pack_f16(float z0, float z1,
                                               uint32_t& hw, uint32_t& lw) {
    __half h0 = __float2half_rn(z0);
    __half h1 = __float2half_rn(z1);
    float r0 = z0 - __half2float(h0);
    float r1 = z1 - __half2float(h1);
    __half2 hp = __halves2half2(h0, h1);
    __half2 lp = __halves2half2(__float2half_rn(r0), __float2half_rn(r1));
    hw = *(uint32_t*)&hp;
    lw = *(uint32_t*)&lp;
}

// ---------------------------------------------------------------------------
// prep: W1..W4 fp32 [256n,256k] -> fp16 k32 chunks, 80B padded rows
// ---------------------------------------------------------------------------
__global__ void prep_weights(const float* __restrict__ W1, const float* __restrict__ W2,
                             const float* __restrict__ W3, const float* __restrict__ W4) {
    int idx = blockIdx.x * blockDim.x + threadIdx.x;   // 65536
    int grp = idx & 7;
    int n   = (idx >> 3) & 255;
    int kc  = (idx >> 11) & 7;
    int l   = idx >> 14;
    const float* W = (l == 0) ? W1 : (l == 1) ? W2 : (l == 2) ? W3 : W4;
    int k0 = kc * 32 + grp * 4;
    __half2 p01 = __halves2half2(__float2half_rn(W[n * 256 + k0]),
                                 __float2half_rn(W[n * 256 + k0 + 1]));
    __half2 p23 = __halves2half2(__float2half_rn(W[n * 256 + k0 + 2]),
                                 __float2half_rn(W[n * 256 + k0 + 3]));
    size_t base = (size_t)(l * 8 + kc) * W_CHUNK + (size_t)n * W_LDB + (size_t)grp * 8;
    *(uint2*)(g_wpacked + base) = make_uint2(*(uint32_t*)&p01, *(uint32_t*)&p23);
}

// ---------------------------------------------------------------------------
// main kernel
// ---------------------------------------------------------------------------
__device__ __forceinline__ void prefetch_chunk(uint32_t sb, int tid, int g) {
    const char* src = (const char*)g_wpacked + (size_t)g * W_CHUNK + (size_t)tid * 16;
    uint32_t dst = sb + WBUF_OFF + (uint32_t)(g & 1) * W_CHUNK + (uint32_t)tid * 16;
#pragma unroll
    for (int i = 0; i < 5; i++)
        CP_ASYNC16(dst + (uint32_t)i * 4096u, src + (size_t)i * 4096);
    CP_COMMIT();
}

__global__ void __launch_bounds__(THREADS, 2)
siren_f16_kernel(const float* __restrict__ xyt, const float* __restrict__ W0,
                 const float* __restrict__ b0, const float* __restrict__ b1,
                 const float* __restrict__ b2, const float* __restrict__ b3,
                 const float* __restrict__ b4, const float* __restrict__ Wf,
                 const float* __restrict__ bfp, float* __restrict__ out) {
    extern __shared__ char smem[];
    const uint32_t sb = smem_u32(smem);
    const int tid = threadIdx.x;
    const int lane = tid & 31;
    const int wid = tid >> 5;
    const int warp_m = wid & 1;    // 2 warp-rows over M (32 rows each)
    const int warp_n = wid >> 1;   // 4 warp-slices over N (64 cols each)

    prefetch_chunk(sb, tid, 0);
    prefetch_chunk(sb, tid, 1);

    float* bias = (float*)(smem + BIAS_OFF);   // b0..b4
    float* Wfs  = (float*)(smem + WFS_OFF);
    if (tid < 256) {
        bias[tid]        = b0[tid];
        bias[256 + tid]  = b1[tid];
        bias[512 + tid]  = b2[tid];
        bias[768 + tid]  = b3[tid];
        bias[1024 + tid] = b4[tid];
        Wfs[tid] = Wf[tid];
    }
    __syncthreads();

    // ---- first layer (SIMT): sin(30*(x@W0^T+b0)) -> A hi plane only ----
    {
        int row   = tid >> 2;                  // 0..63
        int cbase = (tid & 3) * 64;
        int m = blockIdx.x * M_TILE + row;
        float x0 = __ldg(&xyt[3 * m]), x1 = __ldg(&xyt[3 * m + 1]), x2 = __ldg(&xyt[3 * m + 2]);
        char* arow = smem + (uint32_t)row * A_LDB + (uint32_t)cbase * 2;
#pragma unroll 4
        for (int q = 0; q < 32; q++) {
            int n = cbase + 2 * q;
            const float* w = W0 + 3 * n;
            float z0 = fmaf(x0, __ldg(w),     fmaf(x1, __ldg(w + 1), fmaf(x2, __ldg(w + 2), bias[n])));
            float z1 = fmaf(x0, __ldg(w + 3), fmaf(x1, __ldg(w + 4), fmaf(x2, __ldg(w + 5), bias[n + 1])));
            *(uint32_t*)(arow + 4 * q) = pack_f16(__sinf(30.0f * z0), __sinf(30.0f * z1));
        }
    }
    // (first chunk-iteration __syncthreads gates A visibility)

    // ---- hidden layers 1..3: single-fp16 activations, 1 MMA per k16 ----
#pragma unroll 1
    for (int layer = 0; layer < 3; layer++) {
        float acc[2][8][4];
#pragma unroll
        for (int i = 0; i < 2; i++)
#pragma unroll
            for (int j = 0; j < 8; j++)
#pragma unroll
                for (int e = 0; e < 4; e++) acc[i][j][e] = 0.0f;

#pragma unroll 1
        for (int kc = 0; kc < 8; kc++) {
            int g = layer * 8 + kc;
            CP_WAIT(1);
            __syncthreads();
            uint32_t wb = sb + WBUF_OFF + (uint32_t)(g & 1) * W_CHUNK;

#pragma unroll
            for (int ks = 0; ks < 2; ks++) {
                uint32_t bh[4][4];
#pragma unroll
                for (int jj = 0; jj < 4; jj++) {
                    uint32_t baddr = wb
                        + (uint32_t)((warp_n * 64 + jj * 16 + (lane & 7) + ((lane >> 4) * 8)) * W_LDB)
                        + (uint32_t)(ks * 32 + ((lane >> 3) & 1) * 16);
                    LDSM_X4(bh[jj][0], bh[jj][1], bh[jj][2], bh[jj][3], baddr);
                }
#pragma unroll
                for (int i = 0; i < 2; i++) {
                    uint32_t aaddr = sb
                        + (uint32_t)((warp_m * 32 + i * 16 + (lane & 15)) * A_LDB)
                        + (uint32_t)((kc * 2 + ks) * 32 + (lane >> 4) * 16);
                    uint32_t ah0, ah1, ah2, ah3;
                    LDSM_X4(ah0, ah1, ah2, ah3, aaddr);
#pragma unroll
                    for (int j = 0; j < 8; j++) {
                        uint32_t b0r = bh[j >> 1][(j & 1) * 2];
                        uint32_t b1r = bh[j >> 1][(j & 1) * 2 + 1];
                        MMA_F16(acc[i][j], ah0, ah1, ah2, ah3, b0r, b1r);
                    }
                }
            }
            __syncthreads();
            prefetch_chunk(sb, tid, g + 2);
        }

        // ---- epilogue: sin + pack; layer 2 also writes the lo plane ----
        const float* bs = bias + (layer + 1) * 256;
        if (layer < 2) {
#pragma unroll
            for (int i = 0; i < 2; i++) {
                int r0 = warp_m * 32 + i * 16 + (lane >> 2);
#pragma unroll
                for (int j = 0; j < 8; j++) {
                    int n0 = warp_n * 64 + j * 8 + (lane & 3) * 2;
                    uint32_t off = (uint32_t)(r0 * A_LDB + n0 * 2);
                    float bb0 = bs[n0], bb1 = bs[n0 + 1];
                    *(uint32_t*)(smem + off) =
                        pack_f16(__sinf(acc[i][j][0] + bb0), __sinf(acc[i][j][1] + bb1));
                    *(uint32_t*)(smem + off + 8u * A_LDB) =
                        pack_f16(__sinf(acc[i][j][2] + bb0), __sinf(acc[i][j][3] + bb1));
                }
            }
        } else {
#pragma unroll
            for (int i = 0; i < 2; i++) {
                int r0 = warp_m * 32 + i * 16 + (lane >> 2);
#pragma unroll
                for (int j = 0; j < 8; j++) {
                    int n0 = warp_n * 64 + j * 8 + (lane & 3) * 2;
                    uint32_t off = (uint32_t)(r0 * A_LDB + n0 * 2);
                    float bb0 = bs[n0], bb1 = bs[n0 + 1];
                    uint32_t hw, lw;
                    split_pack_f16(__sinf(acc[i][j][0] + bb0), __sinf(acc[i][j][1] + bb1), hw, lw);
                    *(uint32_t*)(smem + off)           = hw;
                    *(uint32_t*)(smem + A_PLANE + off) = lw;
                    split_pack_f16(__sinf(acc[i][j][2] + bb0), __sinf(acc[i][j][3] + bb1), hw, lw);
                    *(uint32_t*)(smem + off + 8u * A_LDB)           = hw;
                    *(uint32_t*)(smem + A_PLANE + off + 8u * A_LDB) = lw;
                }
            }
        }
        // next iteration's post-CP_WAIT __syncthreads gates these writes
    }

    // ---- hidden layer 4: exact hi/lo activations, 2 MMAs per k16 ----
    {
        float acc[2][8][4];
#pragma unroll
        for (int i = 0; i < 2; i++)
#pragma unroll
            for (int j = 0; j < 8; j++)
#pragma unroll
                for (int e = 0; e < 4; e++) acc[i][j][e] = 0.0f;

#pragma unroll 1
        for (int kc = 0; kc < 8; kc++) {
            int g = 24 + kc;
            if (g == 31) { CP_WAIT(0); } else { CP_WAIT(1); }
            __syncthreads();
            uint32_t wb = sb + WBUF_OFF + (uint32_t)(g & 1) * W_CHUNK;

#pragma unroll
            for (int ks = 0; ks < 2; ks++) {
                uint32_t bh[4][4];
#pragma unroll
                for (int jj = 0; jj < 4; jj++) {
                    uint32_t baddr = wb
                        + (uint32_t)((warp_n * 64 + jj * 16 + (lane & 7) + ((lane >> 4) * 8)) * W_LDB)
                        + (uint32_t)(ks * 32 + ((lane >> 3) & 1) * 16);
                    LDSM_X4(bh[jj][0], bh[jj][1], bh[jj][2], bh[jj][3], baddr);
                }
#pragma unroll
                for (int i = 0; i < 2; i++) {
                    uint32_t aaddr = sb
                        + (uint32_t)((warp_m * 32 + i * 16 + (lane & 15)) * A_LDB)
                        + (uint32_t)((kc * 2 + ks) * 32 + (lane >> 4) * 16);
                    uint32_t ah0, ah1, ah2, ah3, al0, al1, al2, al3;
                    LDSM_X4(ah0, ah1, ah2, ah3, aaddr);
                    LDSM_X4(al0, al1, al2, al3, aaddr + A_PLANE);
#pragma unroll
                    for (int j = 0; j < 8; j++) {
                        uint32_t b0r = bh[j >> 1][(j & 1) * 2];
                        uint32_t b1r = bh[j >> 1][(j & 1) * 2 + 1];
                        MMA_F16(acc[i][j], ah0, ah1, ah2, ah3, b0r, b1r);  // hi*w
                        MMA_F16(acc[i][j], al0, al1, al2, al3, b0r, b1r);  // lo*w
                    }
                }
            }
            __syncthreads();
            if (g + 2 < 32) prefetch_chunk(sb, tid, g + 2);   // FIX: keep chain alive
        }

        // ---- final epilogue: out[m] = sum_n sin(z) * Wf[n] + bf ----
        const float* bs = bias + 1024;
        float* red = (float*)(smem + AB_OFF);   // reuse dead A area
#pragma unroll
        for (int i = 0; i < 2; i++) {
            float p0 = 0.0f, p1 = 0.0f;
#pragma unroll
            for (int j = 0; j < 8; j++) {
                int n0 = warp_n * 64 + j * 8 + (lane & 3) * 2;
                p0 = fmaf(__sinf(acc[i][j][0] + bs[n0]),     Wfs[n0],     p0);
                p0 = fmaf(__sinf(acc[i][j][1] + bs[n0 + 1]), Wfs[n0 + 1], p0);
                p1 = fmaf(__sinf(acc[i][j][2] + bs[n0]),     Wfs[n0],     p1);
                p1 = fmaf(__sinf(acc[i][j][3] + bs[n0 + 1]), Wfs[n0 + 1], p1);
            }
            p0 += __shfl_xor_sync(0xffffffffu, p0, 1);
            p0 += __shfl_xor_sync(0xffffffffu, p0, 2);
            p1 += __shfl_xor_sync(0xffffffffu, p1, 1);
            p1 += __shfl_xor_sync(0xffffffffu, p1, 2);
            if ((lane & 3) == 0) {
                int r0 = warp_m * 32 + i * 16 + (lane >> 2);
                red[r0 * 4 + warp_n]       = p0;
                red[(r0 + 8) * 4 + warp_n] = p1;
            }
        }
        __syncthreads();
        if (tid < 64) {
            float s = red[tid * 4] + red[tid * 4 + 1] +
                      red[tid * 4 + 2] + red[tid * 4 + 3] + bfp[0];
            out[(size_t)blockIdx.x * M_TILE + tid] = s;
        }
    }
}

// ---------------------------------------------------------------------------
// kernel_launch
// ---------------------------------------------------------------------------
extern "C" void kernel_launch(void* const* d_in, const int* in_sizes, int n_in,
                              void* d_out, int out_size) {
    const float* xyt = (const float*)d_in[0];
    const float* W0  = (const float*)d_in[1];
    const float* b0  = (const float*)d_in[2];
    const float* W1  = (const float*)d_in[3];
    const float* b1  = (const float*)d_in[4];
    const float* W2  = (const float*)d_in[5];
    const float* b2  = (const float*)d_in[6];
    const float* W3  = (const float*)d_in[7];
    const float* b3  = (const float*)d_in[8];
    const float* W4  = (const float*)d_in[9];
    const float* b4  = (const float*)d_in[10];
    const float* Wf  = (const float*)d_in[11];
    const float* bf  = (const float*)d_in[12];
    float* out = (float*)d_out;
    (void)in_sizes; (void)n_in; (void)out_size;

    cudaFuncSetAttribute(siren_f16_kernel,
                         cudaFuncAttributeMaxDynamicSharedMemorySize, SMEM_TOTAL);

    prep_weights<<<256, 256>>>(W1, W2, W3, W4);
    siren_f16_kernel<<<GRID_CTAS, THREADS, SMEM_TOTAL>>>(
        xyt, W0, b0, b1, b2, b3, b4, Wf, bf, out);
}

// round 10
// speedup vs baseline: 9.8270x; 1.0165x over previous
#include <cuda_runtime.h>
#include <cuda_fp16.h>
#include <cstdint>

// ============================================================================
// SIREN fused inference via fp16 mma.sync m16n8k16 (sm_103-safe PTX).
// R9: all layers single-fp16 activations (1 MMA/k16), 64x64 warp tiles
// (M_TILE=128, 8 warps in 2x4, 1 CTA/SM) to cut SMEM-crossbar (ldmatrix)
// bytes per MAC by 1.5x vs 32x64 tiles. Weights fp16, cp.async k32 chunks.
// Calibrated error model: rel_err ~7.4e-4 (< 1e-3).
// ============================================================================

#define THREADS    256
#define M_TILE     128
#define N_POINTS   1048576
#define GRID_CTAS  (N_POINTS / M_TILE)      // 8192

// --- SMEM layout (bytes) ---
#define A_LDB      528                       // 256 k halves + 16B pad
#define AB_OFF     0                         // single A plane: 128 rows
#define WBUF_OFF   (128 * A_LDB)             // 67584
#define W_LDB      80                        // 32 k halves (64B) + 16B pad
#define W_CHUNK    (256 * W_LDB)             // 20480 (k32 chunk)
#define BIAS_OFF   (WBUF_OFF + 2 * W_CHUNK)  // 108544 : b0..b4 (5*256 f32)
#define WFS_OFF    (BIAS_OFF + 5120)         // 113664 : Wf (256 f32)
#define SMEM_TOTAL (WFS_OFF + 1024)          // 114688
// final-reduction buffer reuses the (dead) A area

// fp16-packed weights: 32 chunks (layer*8 + kc), each 20480B
__device__ __align__(128) unsigned char g_wpacked[32 * W_CHUNK];

// ---------------------------------------------------------------------------
// helpers
// ---------------------------------------------------------------------------
__device__ __forceinline__ uint32_t smem_u32(const void* p) {
    uint32_t a;
    asm("{ .reg .u64 t; cvta.to.shared.u64 t, %1; cvt.u32.u64 %0, t; }"
        : "=r"(a) : "l"(p));
    return a;
}

#define CP_ASYNC16(dst, src) \
    asm volatile("cp.async.cg.shared.global [%0], [%1], 16;" :: "r"(dst), "l"(src) : "memory")
#define CP_COMMIT() asm volatile("cp.async.commit_group;" ::: "memory")
#define CP_WAIT(n)  asm volatile("cp.async.wait_group %0;" :: "n"(n) : "memory")

#define LDSM_X4(r0, r1, r2, r3, addr)                                          \
    asm volatile("ldmatrix.sync.aligned.m8n8.x4.shared.b16 {%0,%1,%2,%3}, [%4];" \
        : "=r"(r0), "=r"(r1), "=r"(r2), "=r"(r3) : "r"(addr))

#define MMA_F16(d, a0, a1, a2, a3, b0, b1)                                     \
    asm volatile("mma.sync.aligned.m16n8k16.row.col.f32.f16.f16.f32 "          \
        "{%0,%1,%2,%3}, {%4,%5,%6,%7}, {%8,%9}, {%0,%1,%2,%3};"                \
        : "+f"((d)[0]), "+f"((d)[1]), "+f"((d)[2]), "+f"((d)[3])               \
        : "r"(a0), "r"(a1), "r"(a2), "r"(a3), "r"(b0), "r"(b1))

// single fp16 pack of two fp32
__device__ __forceinline__ uint32_t pack_f16(float z0, float z1) {
    __half2 hp = __halves2half2(__float2half_rn(z0), __float2half_rn(z1));
    return *(uint32_t*)&hp;
}

// ---------------------------------------------------------------------------
// prep: W1..W4 fp32 [256n,256k] -> fp16 k32 chunks, 80B padded rows
// ---------------------------------------------------------------------------
__global__ void prep_weights(const float* __restrict__ W1, const float* __restrict__ W2,
                             const float* __restrict__ W3, const float* __restrict__ W4) {
    int idx = blockIdx.x * blockDim.x + threadIdx.x;   // 65536
    int grp = idx & 7;
    int n   = (idx >> 3) & 255;
    int kc  = (idx >> 11) & 7;
    int l   = idx >> 14;
    const float* W = (l == 0) ? W1 : (l == 1) ? W2 : (l == 2) ? W3 : W4;
    int k0 = kc * 32 + grp * 4;
    __half2 p01 = __halves2half2(__float2half_rn(W[n * 256 + k0]),
                                 __float2half_rn(W[n * 256 + k0 + 1]));
    __half2 p23 = __halves2half2(__float2half_rn(W[n * 256 + k0 + 2]),
                                 __float2half_rn(W[n * 256 + k0 + 3]));
    size_t base = (size_t)(l * 8 + kc) * W_CHUNK + (size_t)n * W_LDB + (size_t)grp * 8;
    *(uint2*)(g_wpacked + base) = make_uint2(*(uint32_t*)&p01, *(uint32_t*)&p23);
}

// ---------------------------------------------------------------------------
// main kernel
// ---------------------------------------------------------------------------
__device__ __forceinline__ void prefetch_chunk(uint32_t sb, int tid, int g) {
    const char* src = (const char*)g_wpacked + (size_t)g * W_CHUNK + (size_t)tid * 16;
    uint32_t dst = sb + WBUF_OFF + (uint32_t)(g & 1) * W_CHUNK + (uint32_t)tid * 16;
#pragma unroll
    for (int i = 0; i < 5; i++)
        CP_ASYNC16(dst + (uint32_t)i * 4096u, src + (size_t)i * 4096);
    CP_COMMIT();
}

__global__ void __launch_bounds__(THREADS, 1)
siren_f16_kernel(const float* __restrict__ xyt, const float* __restrict__ W0,
                 const float* __restrict__ b0, const float* __restrict__ b1,
                 const float* __restrict__ b2, const float* __restrict__ b3,
                 const float* __restrict__ b4, const float* __restrict__ Wf,
                 const float* __restrict__ bfp, float* __restrict__ out) {
    extern __shared__ char smem[];
    const uint32_t sb = smem_u32(smem);
    const int tid = threadIdx.x;
    const int lane = tid & 31;
    const int wid = tid >> 5;
    const int warp_m = wid & 1;    // 2 warp-rows over M (64 rows each)
    const int warp_n = wid >> 1;   // 4 warp-slices over N (64 cols each)

    prefetch_chunk(sb, tid, 0);
    prefetch_chunk(sb, tid, 1);

    float* bias = (float*)(smem + BIAS_OFF);   // b0..b4
    float* Wfs  = (float*)(smem + WFS_OFF);
    if (tid < 256) {
        bias[tid]        = b0[tid];
        bias[256 + tid]  = b1[tid];
        bias[512 + tid]  = b2[tid];
        bias[768 + tid]  = b3[tid];
        bias[1024 + tid] = b4[tid];
        Wfs[tid] = Wf[tid];
    }
    __syncthreads();

    // ---- first layer (SIMT): sin(30*(x@W0^T+b0)) -> A plane ----
    {
        int row   = tid >> 1;                  // 0..127 (2 threads per row)
        int cbase = (tid & 1) * 128;           // 128 n-cols per thread
        int m = blockIdx.x * M_TILE + row;
        float x0 = __ldg(&xyt[3 * m]), x1 = __ldg(&xyt[3 * m + 1]), x2 = __ldg(&xyt[3 * m + 2]);
        char* arow = smem + (uint32_t)row * A_LDB + (uint32_t)cbase * 2;
#pragma unroll 4
        for (int q = 0; q < 64; q++) {
            int n = cbase + 2 * q;
            const float* w = W0 + 3 * n;
            float z0 = fmaf(x0, __ldg(w),     fmaf(x1, __ldg(w + 1), fmaf(x2, __ldg(w + 2), bias[n])));
            float z1 = fmaf(x0, __ldg(w + 3), fmaf(x1, __ldg(w + 4), fmaf(x2, __ldg(w + 5), bias[n + 1])));
            *(uint32_t*)(arow + 4 * q) = pack_f16(__sinf(30.0f * z0), __sinf(30.0f * z1));
        }
    }
    // (first chunk-iteration __syncthreads gates A visibility)

    // ---- 4 hidden layers: single-fp16 activations, 64x64 warp tiles ----
#pragma unroll 1
    for (int layer = 0; layer < 4; layer++) {
        float acc[4][8][4];
#pragma unroll
        for (int i = 0; i < 4; i++)
#pragma unroll
            for (int j = 0; j < 8; j++)
#pragma unroll
                for (int e = 0; e < 4; e++) acc[i][j][e] = 0.0f;

#pragma unroll 1
        for (int kc = 0; kc < 8; kc++) {
            int g = layer * 8 + kc;
            if (g == 31) { CP_WAIT(0); } else { CP_WAIT(1); }
            __syncthreads();
            uint32_t wb = sb + WBUF_OFF + (uint32_t)(g & 1) * W_CHUNK;

#pragma unroll
            for (int ks = 0; ks < 2; ks++) {
                // B fragments: 4 x4-ldsm covering 64 n-rows x k16
                uint32_t bh[4][4];
#pragma unroll
                for (int jj = 0; jj < 4; jj++) {
                    uint32_t baddr = wb
                        + (uint32_t)((warp_n * 64 + jj * 16 + (lane & 7) + ((lane >> 4) * 8)) * W_LDB)
                        + (uint32_t)(ks * 32 + ((lane >> 3) & 1) * 16);
                    LDSM_X4(bh[jj][0], bh[jj][1], bh[jj][2], bh[jj][3], baddr);
                }
#pragma unroll
                for (int i = 0; i < 4; i++) {
                    uint32_t aaddr = sb
                        + (uint32_t)((warp_m * 64 + i * 16 + (lane & 15)) * A_LDB)
                        + (uint32_t)((kc * 2 + ks) * 32 + (lane >> 4) * 16);
                    uint32_t ah0, ah1, ah2, ah3;
                    LDSM_X4(ah0, ah1, ah2, ah3, aaddr);
#pragma unroll
                    for (int j = 0; j < 8; j++) {
                        uint32_t b0r = bh[j >> 1][(j & 1) * 2];
                        uint32_t b1r = bh[j >> 1][(j & 1) * 2 + 1];
                        MMA_F16(acc[i][j], ah0, ah1, ah2, ah3, b0r, b1r);
                    }
                }
            }
            __syncthreads();
            if (g + 2 < 32) prefetch_chunk(sb, tid, g + 2);
        }

        // ---- epilogue ----
        if (layer < 3) {
            const float* bs = bias + (layer + 1) * 256;
#pragma unroll
            for (int i = 0; i < 4; i++) {
                int r0 = warp_m * 64 + i * 16 + (lane >> 2);
#pragma unroll
                for (int j = 0; j < 8; j++) {
                    int n0 = warp_n * 64 + j * 8 + (lane & 3) * 2;
                    uint32_t off = (uint32_t)(r0 * A_LDB + n0 * 2);
                    float bb0 = bs[n0], bb1 = bs[n0 + 1];
                    *(uint32_t*)(smem + off) =
                        pack_f16(__sinf(acc[i][j][0] + bb0), __sinf(acc[i][j][1] + bb1));
                    *(uint32_t*)(smem + off + 8u * A_LDB) =
                        pack_f16(__sinf(acc[i][j][2] + bb0), __sinf(acc[i][j][3] + bb1));
                }
            }
            // next iteration's post-CP_WAIT __syncthreads gates these writes
        } else {
            // final: out[m] = sum_n sin(z[m,n]) * Wf[n] + bf
            const float* bs = bias + 1024;
            float* red = (float*)(smem + AB_OFF);   // reuse dead A area
#pragma unroll
            for (int i = 0; i < 4; i++) {
                float p0 = 0.0f, p1 = 0.0f;
#pragma unroll
                for (int j = 0; j < 8; j++) {
                    int n0 = warp_n * 64 + j * 8 + (lane & 3) * 2;
                    p0 = fmaf(__sinf(acc[i][j][0] + bs[n0]),     Wfs[n0],     p0);
                    p0 = fmaf(__sinf(acc[i][j][1] + bs[n0 + 1]), Wfs[n0 + 1], p0);
                    p1 = fmaf(__sinf(acc[i][j][2] + bs[n0]),     Wfs[n0],     p1);
                    p1 = fmaf(__sinf(acc[i][j][3] + bs[n0 + 1]), Wfs[n0 + 1], p1);
                }
                p0 += __shfl_xor_sync(0xffffffffu, p0, 1);
                p0 += __shfl_xor_sync(0xffffffffu, p0, 2);
                p1 += __shfl_xor_sync(0xffffffffu, p1, 1);
                p1 += __shfl_xor_sync(0xffffffffu, p1, 2);
                if ((lane & 3) == 0) {
                    int r0 = warp_m * 64 + i * 16 + (lane >> 2);
                    red[r0 * 4 + warp_n]       = p0;
                    red[(r0 + 8) * 4 + warp_n] = p1;
                }
            }
            __syncthreads();
            if (tid < 128) {
                float s = red[tid * 4] + red[tid * 4 + 1] +
                          red[tid * 4 + 2] + red[tid * 4 + 3] + bfp[0];
                out[(size_t)blockIdx.x * M_TILE + tid] = s;
            }
        }
    }
}

// ---------------------------------------------------------------------------
// kernel_launch
// ---------------------------------------------------------------------------
extern "C" void kernel_launch(void* const* d_in, const int* in_sizes, int n_in,
                              void* d_out, int out_size) {
    const float* xyt = (const float*)d_in[0];
    const float* W0  = (const float*)d_in[1];
    const float* b0  = (const float*)d_in[2];
    const float* W1  = (const float*)d_in[3];
    const float* b1  = (const float*)d_in[4];
    const float* W2  = (const float*)d_in[5];
    const float* b2  = (const float*)d_in[6];
    const float* W3  = (const float*)d_in[7];
    const float* b3  = (const float*)d_in[8];
    const float* W4  = (const float*)d_in[9];
    const float* b4  = (const float*)d_in[10];
    const float* Wf  = (const float*)d_in[11];
    const float* bf  = (const float*)d_in[12];
    float* out = (float*)d_out;
    (void)in_sizes; (void)n_in; (void)out_size;

    cudaFuncSetAttribute(siren_f16_kernel,
                         cudaFuncAttributeMaxDynamicSharedMemorySize, SMEM_TOTAL);

    prep_weights<<<256, 256>>>(W1, W2, W3, W4);
    siren_f16_kernel<<<GRID_CTAS, THREADS, SMEM_TOTAL>>>(
        xyt, W0, b0, b1, b2, b3, b4, Wf, bf, out);
}

// round 11
// speedup vs baseline: 10.9083x; 1.1100x over previous
#include <cuda_runtime.h>
#include <cuda_fp16.h>
#include <cstdint>

// ============================================================================
// SIREN fused inference via fp16 mma.sync m16n8k16 (sm_103-safe PTX).
// R11 = R9 geometry (M_TILE=64, 2 CTAs/SM, 32x64 warp tiles -> cross-CTA
// overlap of sin/ldsm with HMMA) + R10 numerics (single fp16 activations on
// ALL layers, 1 MMA/k16) + k64 weight chunks (half the barriers).
// rel_err model: 6.6e-4 (validated in R10).
// ============================================================================

#define THREADS    256
#define M_TILE     64
#define N_POINTS   1048576
#define GRID_CTAS  (N_POINTS / M_TILE)      // 16384

// --- SMEM layout (bytes) ---
#define A_LDB      528                       // 256 k halves + 16B pad
#define AB_OFF     0                         // single A plane: 64 rows
#define WBUF_OFF   (64 * A_LDB)              // 33792
#define W_LDB      144                       // 64 k halves (128B) + 16B pad
#define W_CHUNK    (256 * W_LDB)             // 36864 (k64 chunk)
#define BIAS_OFF   (WBUF_OFF + 2 * W_CHUNK)  // 107520 : b0..b4 (5*256 f32)
#define WFS_OFF    (BIAS_OFF + 5120)         // 112640 : Wf (256 f32)
#define SMEM_TOTAL (WFS_OFF + 1024)          // 113664 -> 2 CTAs/SM
// final-reduction buffer reuses the (dead) A area

// fp16-packed weights: 16 chunks (layer*4 + kc), each 36864B
__device__ __align__(128) unsigned char g_wpacked[16 * W_CHUNK];

// ---------------------------------------------------------------------------
// helpers
// ---------------------------------------------------------------------------
__device__ __forceinline__ uint32_t smem_u32(const void* p) {
    uint32_t a;
    asm("{ .reg .u64 t; cvta.to.shared.u64 t, %1; cvt.u32.u64 %0, t; }"
        : "=r"(a) : "l"(p));
    return a;
}

#define CP_ASYNC16(dst, src) \
    asm volatile("cp.async.cg.shared.global [%0], [%1], 16;" :: "r"(dst), "l"(src) : "memory")
#define CP_COMMIT() asm volatile("cp.async.commit_group;" ::: "memory")
#define CP_WAIT(n)  asm volatile("cp.async.wait_group %0;" :: "n"(n) : "memory")

#define LDSM_X4(r0, r1, r2, r3, addr)                                          \
    asm volatile("ldmatrix.sync.aligned.m8n8.x4.shared.b16 {%0,%1,%2,%3}, [%4];" \
        : "=r"(r0), "=r"(r1), "=r"(r2), "=r"(r3) : "r"(addr))

#define MMA_F16(d, a0, a1, a2, a3, b0, b1)                                     \
    asm volatile("mma.sync.aligned.m16n8k16.row.col.f32.f16.f16.f32 "          \
        "{%0,%1,%2,%3}, {%4,%5,%6,%7}, {%8,%9}, {%0,%1,%2,%3};"                \
        : "+f"((d)[0]), "+f"((d)[1]), "+f"((d)[2]), "+f"((d)[3])               \
        : "r"(a0), "r"(a1), "r"(a2), "r"(a3), "r"(b0), "r"(b1))

// single fp16 pack of two fp32
__device__ __forceinline__ uint32_t pack_f16(float z0, float z1) {
    __half2 hp = __halves2half2(__float2half_rn(z0), __float2half_rn(z1));
    return *(uint32_t*)&hp;
}

// ---------------------------------------------------------------------------
// prep: W1..W4 fp32 [256n,256k] -> fp16 k64 chunks, 144B padded rows
// ---------------------------------------------------------------------------
__global__ void prep_weights(const float* __restrict__ W1, const float* __restrict__ W2,
                             const float* __restrict__ W3, const float* __restrict__ W4) {
    int idx = blockIdx.x * blockDim.x + threadIdx.x;   // 65536
    int kg = idx & 63;                                 // 4-k group within 256
    int n  = (idx >> 6) & 255;
    int l  = idx >> 14;
    const float* W = (l == 0) ? W1 : (l == 1) ? W2 : (l == 2) ? W3 : W4;
    int k0 = kg * 4;
    __half2 p01 = __halves2half2(__float2half_rn(W[n * 256 + k0]),
                                 __float2half_rn(W[n * 256 + k0 + 1]));
    __half2 p23 = __halves2half2(__float2half_rn(W[n * 256 + k0 + 2]),
                                 __float2half_rn(W[n * 256 + k0 + 3]));
    int kc = k0 >> 6;                                  // k64 chunk in layer
    int kl = k0 & 63;
    size_t base = (size_t)(l * 4 + kc) * W_CHUNK + (size_t)n * W_LDB + (size_t)kl * 2;
    *(uint2*)(g_wpacked + base) = make_uint2(*(uint32_t*)&p01, *(uint32_t*)&p23);
}

// ---------------------------------------------------------------------------
// main kernel
// ---------------------------------------------------------------------------
__device__ __forceinline__ void prefetch_chunk(uint32_t sb, int tid, int g) {
    const char* src = (const char*)g_wpacked + (size_t)g * W_CHUNK + (size_t)tid * 16;
    uint32_t dst = sb + WBUF_OFF + (uint32_t)(g & 1) * W_CHUNK + (uint32_t)tid * 16;
#pragma unroll
    for (int i = 0; i < 9; i++)
        CP_ASYNC16(dst + (uint32_t)i * 4096u, src + (size_t)i * 4096);
    CP_COMMIT();
}

__global__ void __launch_bounds__(THREADS, 2)
siren_f16_kernel(const float* __restrict__ xyt, const float* __restrict__ W0,
                 const float* __restrict__ b0, const float* __restrict__ b1,
                 const float* __restrict__ b2, const float* __restrict__ b3,
                 const float* __restrict__ b4, const float* __restrict__ Wf,
                 const float* __restrict__ bfp, float* __restrict__ out) {
    extern __shared__ char smem[];
    const uint32_t sb = smem_u32(smem);
    const int tid = threadIdx.x;
    const int lane = tid & 31;
    const int wid = tid >> 5;
    const int warp_m = wid & 1;    // 2 warp-rows over M (32 rows each)
    const int warp_n = wid >> 1;   // 4 warp-slices over N (64 cols each)

    prefetch_chunk(sb, tid, 0);
    prefetch_chunk(sb, tid, 1);

    float* bias = (float*)(smem + BIAS_OFF);   // b0..b4
    float* Wfs  = (float*)(smem + WFS_OFF);
    if (tid < 256) {
        bias[tid]        = b0[tid];
        bias[256 + tid]  = b1[tid];
        bias[512 + tid]  = b2[tid];
        bias[768 + tid]  = b3[tid];
        bias[1024 + tid] = b4[tid];
        Wfs[tid] = Wf[tid];
    }
    __syncthreads();

    // ---- first layer (SIMT): sin(30*(x@W0^T+b0)) -> A plane ----
    {
        int row   = tid >> 2;                  // 0..63
        int cbase = (tid & 3) * 64;            // 64 n-cols per thread
        int m = blockIdx.x * M_TILE + row;
        float x0 = __ldg(&xyt[3 * m]), x1 = __ldg(&xyt[3 * m + 1]), x2 = __ldg(&xyt[3 * m + 2]);
        char* arow = smem + (uint32_t)row * A_LDB + (uint32_t)cbase * 2;
#pragma unroll 4
        for (int q = 0; q < 32; q++) {
            int n = cbase + 2 * q;
            const float* w = W0 + 3 * n;
            float z0 = fmaf(x0, __ldg(w),     fmaf(x1, __ldg(w + 1), fmaf(x2, __ldg(w + 2), bias[n])));
            float z1 = fmaf(x0, __ldg(w + 3), fmaf(x1, __ldg(w + 4), fmaf(x2, __ldg(w + 5), bias[n + 1])));
            *(uint32_t*)(arow + 4 * q) = pack_f16(__sinf(30.0f * z0), __sinf(30.0f * z1));
        }
    }
    // (first chunk-iteration __syncthreads gates A visibility)

    // ---- 4 hidden layers: single-fp16 activations, 32x64 warp tiles ----
#pragma unroll 1
    for (int layer = 0; layer < 4; layer++) {
        float acc[2][8][4];
#pragma unroll
        for (int i = 0; i < 2; i++)
#pragma unroll
            for (int j = 0; j < 8; j++)
#pragma unroll
                for (int e = 0; e < 4; e++) acc[i][j][e] = 0.0f;

#pragma unroll 1
        for (int kc = 0; kc < 4; kc++) {
            int g = layer * 4 + kc;
            if (g == 15) { CP_WAIT(0); } else { CP_WAIT(1); }
            __syncthreads();
            uint32_t wb = sb + WBUF_OFF + (uint32_t)(g & 1) * W_CHUNK;

#pragma unroll
            for (int ks = 0; ks < 4; ks++) {
                // B fragments: 4 x4-ldsm covering 64 n-rows x k16
                uint32_t bh[4][4];
#pragma unroll
                for (int jj = 0; jj < 4; jj++) {
                    uint32_t baddr = wb
                        + (uint32_t)((warp_n * 64 + jj * 16 + (lane & 7) + ((lane >> 4) * 8)) * W_LDB)
                        + (uint32_t)(ks * 32 + ((lane >> 3) & 1) * 16);
                    LDSM_X4(bh[jj][0], bh[jj][1], bh[jj][2], bh[jj][3], baddr);
                }
#pragma unroll
                for (int i = 0; i < 2; i++) {
                    uint32_t aaddr = sb
                        + (uint32_t)((warp_m * 32 + i * 16 + (lane & 15)) * A_LDB)
                        + (uint32_t)((kc * 4 + ks) * 32 + (lane >> 4) * 16);
                    uint32_t ah0, ah1, ah2, ah3;
                    LDSM_X4(ah0, ah1, ah2, ah3, aaddr);
#pragma unroll
                    for (int j = 0; j < 8; j++) {
                        uint32_t b0r = bh[j >> 1][(j & 1) * 2];
                        uint32_t b1r = bh[j >> 1][(j & 1) * 2 + 1];
                        MMA_F16(acc[i][j], ah0, ah1, ah2, ah3, b0r, b1r);
                    }
                }
            }
            __syncthreads();
            if (g + 2 < 16) prefetch_chunk(sb, tid, g + 2);
        }

        // ---- epilogue ----
        if (layer < 3) {
            const float* bs = bias + (layer + 1) * 256;
#pragma unroll
            for (int i = 0; i < 2; i++) {
                int r0 = warp_m * 32 + i * 16 + (lane >> 2);
#pragma unroll
                for (int j = 0; j < 8; j++) {
                    int n0 = warp_n * 64 + j * 8 + (lane & 3) * 2;
                    uint32_t off = (uint32_t)(r0 * A_LDB + n0 * 2);
                    float bb0 = bs[n0], bb1 = bs[n0 + 1];
                    *(uint32_t*)(smem + off) =
                        pack_f16(__sinf(acc[i][j][0] + bb0), __sinf(acc[i][j][1] + bb1));
                    *(uint32_t*)(smem + off + 8u * A_LDB) =
                        pack_f16(__sinf(acc[i][j][2] + bb0), __sinf(acc[i][j][3] + bb1));
                }
            }
            // next iteration's post-CP_WAIT __syncthreads gates these writes
        } else {
            // final: out[m] = sum_n sin(z[m,n]) * Wf[n] + bf
            const float* bs = bias + 1024;
            float* red = (float*)(smem + AB_OFF);   // reuse dead A area
#pragma unroll
            for (int i = 0; i < 2; i++) {
                float p0 = 0.0f, p1 = 0.0f;
#pragma unroll
                for (int j = 0; j < 8; j++) {
                    int n0 = warp_n * 64 + j * 8 + (lane & 3) * 2;
                    p0 = fmaf(__sinf(acc[i][j][0] + bs[n0]),     Wfs[n0],     p0);
                    p0 = fmaf(__sinf(acc[i][j][1] + bs[n0 + 1]), Wfs[n0 + 1], p0);
                    p1 = fmaf(__sinf(acc[i][j][2] + bs[n0]),     Wfs[n0],     p1);
                    p1 = fmaf(__sinf(acc[i][j][3] + bs[n0 + 1]), Wfs[n0 + 1], p1);
                }
                p0 += __shfl_xor_sync(0xffffffffu, p0, 1);
                p0 += __shfl_xor_sync(0xffffffffu, p0, 2);
                p1 += __shfl_xor_sync(0xffffffffu, p1, 1);
                p1 += __shfl_xor_sync(0xffffffffu, p1, 2);
                if ((lane & 3) == 0) {
                    int r0 = warp_m * 32 + i * 16 + (lane >> 2);
                    red[r0 * 4 + warp_n]       = p0;
                    red[(r0 + 8) * 4 + warp_n] = p1;
                }
            }
            __syncthreads();
            if (tid < 64) {
                float s = red[tid * 4] + red[tid * 4 + 1] +
                          red[tid * 4 + 2] + red[tid * 4 + 3] + bfp[0];
                out[(size_t)blockIdx.x * M_TILE + tid] = s;
            }
        }
    }
}

// ---------------------------------------------------------------------------
// kernel_launch
// ---------------------------------------------------------------------------
extern "C" void kernel_launch(void* const* d_in, const int* in_sizes, int n_in,
                              void* d_out, int out_size) {
    const float* xyt = (const float*)d_in[0];
    const float* W0  = (const float*)d_in[1];
    const float* b0  = (const float*)d_in[2];
    const float* W1  = (const float*)d_in[3];
    const float* b1  = (const float*)d_in[4];
    const float* W2  = (const float*)d_in[5];
    const float* b2  = (const float*)d_in[6];
    const float* W3  = (const float*)d_in[7];
    const float* b3  = (const float*)d_in[8];
    const float* W4  = (const float*)d_in[9];
    const float* b4  = (const float*)d_in[10];
    const float* Wf  = (const float*)d_in[11];
    const float* bf  = (const float*)d_in[12];
    float* out = (float*)d_out;
    (void)in_sizes; (void)n_in; (void)out_size;

    cudaFuncSetAttribute(siren_f16_kernel,
                         cudaFuncAttributeMaxDynamicSharedMemorySize, SMEM_TOTAL);

    prep_weights<<<256, 256>>>(W1, W2, W3, W4);
    siren_f16_kernel<<<GRID_CTAS, THREADS, SMEM_TOTAL>>>(
        xyt, W0, b0, b1, b2, b3, b4, Wf, bf, out);
}